// round 15
// baseline (speedup 1.0000x reference)
#include <cuda_runtime.h>
#include <cuda_fp16.h>
#include <stdint.h>
#include <math.h>

#define NN 50000
#define EE 800000
#define IND 256
#define HD  256
#define EPS 1e-5f

// ---------------- scratch (device globals; no allocation allowed) ----------------
__device__ __align__(16) float g_deg[NN];
__device__ __align__(16) float g_dinv[NN];
__device__ __align__(16) float g_norm[EE];
__device__ __align__(16) __half g_XWh[(size_t)NN * HD];      // GEMM out (fp16), gather source
__device__ __align__(16) float g_agg[(size_t)NN * HD];       // relu'd GCN output (fp32)
__device__ __align__(16) __half g_Gh[(size_t)NN * 768];      // packed LSTM gates (i,g,o) fp16
__device__ __align__(16) __half g_xh[(size_t)NN * IND];      // fp16 x
__device__ __align__(16) __half g_XcH[(size_t)NN * 512];     // fp16 [h1|h2] stride 512
__device__ __align__(16) __half g_hL1h[(size_t)NN * HD];     // fp16 hL1
__device__ __align__(16) __half g_W1h[HD * IND];             // W1^T [N,K]
__device__ __align__(16) __half g_W2h[HD * HD];              // W2^T [N,K]
__device__ __align__(16) __half g_B1h[768 * 512];            // packed Wih1 (i,g,o) [N=768,K=512]
__device__ __align__(16) __half g_B2h[768 * 256];            // packed Wih2 [N=768,K=256]
__device__ __align__(16) float g_bias1[768];
__device__ __align__(16) float g_bias2[768];
__device__ __align__(16) float g_sumA[HD];
__device__ __align__(16) float g_sumsqA[HD];
__device__ __align__(16) float g_sumB[HD];
__device__ __align__(16) float g_sumsqB[HD];
// CSR
__device__ int g_cnt[NN];
__device__ int g_rowptr[NN + 1];
__device__ int g_eidx[EE];
__device__ int g_bsum[128];

__device__ __forceinline__ uint32_t smem_u32(const void* p) {
    uint32_t a;
    asm("{ .reg .u64 t; cvta.to.shared.u64 t, %1; cvt.u32.u64 %0, t; }" : "=r"(a) : "l"(p));
    return a;
}

// ---------------- degree / norm / CSR build ----------------
__global__ void k_zero_nd() {
    int i = blockIdx.x * blockDim.x + threadIdx.x;
    if (i < NN) { g_deg[i] = 0.f; g_cnt[i] = 0; }
    if (i < HD) { g_sumA[i] = 0.f; g_sumsqA[i] = 0.f; g_sumB[i] = 0.f; g_sumsqB[i] = 0.f; }
}

__global__ void k_deg_hist(const int* __restrict__ ei, const float* __restrict__ ew) {
    int e = blockIdx.x * blockDim.x + threadIdx.x;
    if (e < EE) {
        int d = ei[EE + e];
        atomicAdd(&g_deg[d], ew[e]);
        atomicAdd(&g_cnt[d], 1);
    }
}

__global__ void k_dinv() {
    int i = blockIdx.x * blockDim.x + threadIdx.x;
    if (i < NN) g_dinv[i] = rsqrtf(g_deg[i] + 1.0f);
}

__global__ void k_norm(const int* __restrict__ ei, const float* __restrict__ ew) {
    int e = blockIdx.x * blockDim.x + threadIdx.x;
    if (e < EE) {
        int s = ei[e], d = ei[EE + e];
        g_norm[e] = g_dinv[s] * ew[e] * g_dinv[d];
    }
}

__global__ void k_scan1() {
    __shared__ int s[512];
    int tid = threadIdx.x;
    int i = blockIdx.x * 512 + tid;
    int v = (i < NN) ? g_cnt[i] : 0;
    s[tid] = v;
    __syncthreads();
    for (int off = 1; off < 512; off <<= 1) {
        int t = (tid >= off) ? s[tid - off] : 0;
        __syncthreads();
        s[tid] += t;
        __syncthreads();
    }
    if (i < NN) g_rowptr[i + 1] = s[tid];
    if (tid == 511) g_bsum[blockIdx.x] = s[511];
}

__global__ void k_scan2(int nb) {
    __shared__ int s[128];
    int tid = threadIdx.x;
    int v = (tid < nb) ? g_bsum[tid] : 0;
    s[tid] = v;
    __syncthreads();
    for (int off = 1; off < 128; off <<= 1) {
        int t = (tid >= off) ? s[tid - off] : 0;
        __syncthreads();
        s[tid] += t;
        __syncthreads();
    }
    if (tid < nb) g_bsum[tid] = s[tid];
}

__global__ void k_scan3() {
    int i = blockIdx.x * blockDim.x + threadIdx.x;
    if (i < NN) {
        int b = i >> 9;
        int add = (b > 0) ? g_bsum[b - 1] : 0;
        g_rowptr[i + 1] += add;
        g_cnt[i] = 0;
    }
    if (i == 0) g_rowptr[0] = 0;
}

__global__ void k_fill(const int* __restrict__ ei) {
    int e = blockIdx.x * blockDim.x + threadIdx.x;
    if (e < EE) {
        int d = ei[EE + e];
        int pos = atomicAdd(&g_cnt[d], 1);
        g_eidx[g_rowptr[d] + pos] = e;
    }
}

// ---------------- CSR aggregation: block per node, 8 warps edge-parallel, uint4 lanes ----------------
__global__ __launch_bounds__(256)
void k_aggregate(const int* __restrict__ ei, const float* __restrict__ bias) {
    __shared__ float part[7][256];
    int n = blockIdx.x;
    int t = threadIdx.x;
    int w = t >> 5;          // warp/group 0..7
    int j = t & 31;          // uint4 index: 8 halfs each
    const uint4* XW = (const uint4*)g_XWh;   // 32 uint4 per row

    float acc[8];
#pragma unroll
    for (int p = 0; p < 8; p++) acc[p] = 0.f;

    int beg = g_rowptr[n], end = g_rowptr[n + 1];
    for (int k = beg + w; k < end; k += 8) {
        int e = g_eidx[k];
        float wgt = g_norm[e];
        int s = ei[e];
        uint4 v = XW[(size_t)s * 32 + j];
        const __half2* h2 = (const __half2*)&v;
#pragma unroll
        for (int p = 0; p < 4; p++) {
            float2 f = __half22float2(h2[p]);
            acc[2 * p]     += f.x * wgt;
            acc[2 * p + 1] += f.y * wgt;
        }
    }
    if (w) {
#pragma unroll
        for (int p = 0; p < 8; p++) part[w - 1][j * 8 + p] = acc[p];
    }
    __syncthreads();
    if (w == 0) {
#pragma unroll
        for (int q = 0; q < 7; q++)
#pragma unroll
            for (int p = 0; p < 8; p++) acc[p] += part[q][j * 8 + p];
        float d = g_dinv[n]; d *= d;
        uint4 sv = XW[(size_t)n * 32 + j];
        const __half2* sh = (const __half2*)&sv;
        float r[8];
#pragma unroll
        for (int p = 0; p < 4; p++) {
            float2 f = __half22float2(sh[p]);
            r[2 * p]     = acc[2 * p]     + f.x * d;
            r[2 * p + 1] = acc[2 * p + 1] + f.y * d;
        }
        const float4* b4 = (const float4*)bias;
        float4 ba = b4[j * 2], bb = b4[j * 2 + 1];
        float4 o1, o2;
        o1.x = fmaxf(r[0] + ba.x, 0.f); o1.y = fmaxf(r[1] + ba.y, 0.f);
        o1.z = fmaxf(r[2] + ba.z, 0.f); o1.w = fmaxf(r[3] + ba.w, 0.f);
        o2.x = fmaxf(r[4] + bb.x, 0.f); o2.y = fmaxf(r[5] + bb.y, 0.f);
        o2.z = fmaxf(r[6] + bb.z, 0.f); o2.w = fmaxf(r[7] + bb.w, 0.f);
        ((float4*)g_agg)[(size_t)n * 64 + j * 2]     = o1;
        ((float4*)g_agg)[(size_t)n * 64 + j * 2 + 1] = o2;
    }
}

// ---------------- misc elementwise ----------------
__global__ void k_tohalf(const float* __restrict__ in, __half* __restrict__ out, long long n) {
    long long i = ((long long)blockIdx.x * blockDim.x + threadIdx.x) * 4;
    if (i + 3 < n) {
        float4 v = *(const float4*)&in[i];
        *(__half2*)&out[i]     = __floats2half2_rn(v.x, v.y);
        *(__half2*)&out[i + 2] = __floats2half2_rn(v.z, v.w);
    } else {
        for (long long k = i; k < n; k++) out[k] = __float2half(in[k]);
    }
}

// W [K=256,N=256] -> Wt half [N,K]
__global__ void k_w_t(const float* __restrict__ W, __half* __restrict__ Wt) {
    int idx = blockIdx.x * blockDim.x + threadIdx.x;
    if (idx >= 256 * 256) return;
    int n = idx >> 8, k = idx & 255;
    Wt[n * 256 + k] = __float2half(W[k * 256 + n]);
}

__global__ void k_bn_stats(float* __restrict__ sum, float* __restrict__ sumsq) {
    const int ROWS = 32;
    int j = threadIdx.x;
    int r0 = blockIdx.x * ROWS;
    int r1 = min(r0 + ROWS, NN);
    float s = 0.f, sq = 0.f;
    for (int r = r0; r < r1; r++) {
        float v = g_agg[(size_t)r * HD + j];
        s += v; sq += v * v;
    }
    atomicAdd(&sum[j], s);
    atomicAdd(&sumsq[j], sq);
}

// fused finalize+apply
__global__ void k_bn_apply(int col_off, const float* __restrict__ sum,
                           const float* __restrict__ sumsq,
                           const float* __restrict__ gamma, const float* __restrict__ beta) {
    size_t idx = (size_t)blockIdx.x * blockDim.x + threadIdx.x;
    if (idx >= (size_t)NN * HD) return;
    int r = (int)(idx >> 8);
    int j = (int)(idx & 255);
    float mu  = sum[j] * (1.f / (float)NN);
    float var = sumsq[j] * (1.f / (float)NN) - mu * mu;
    float sc  = gamma[j] * rsqrtf(var + EPS);
    float sh  = beta[j] - mu * sc;
    float v = g_agg[idx];
    g_XcH[(size_t)r * 512 + col_off + j] = __float2half(v * sc + sh);
}

__global__ void k_pack_w(const float* __restrict__ Wih, __half* __restrict__ Bp, int Kdim) {
    size_t idx = (size_t)blockIdx.x * blockDim.x + threadIdx.x;
    if (idx >= (size_t)768 * Kdim) return;
    int n = (int)(idx / Kdim);
    int k = (int)(idx % Kdim);
    int orig = n + (n >= 256 ? 256 : 0);
    Bp[idx] = __float2half(Wih[(size_t)orig * Kdim + k]);
}

__global__ void k_pack_bias(const float* __restrict__ bih, const float* __restrict__ bhh,
                            float* __restrict__ bp) {
    int n = blockIdx.x * blockDim.x + threadIdx.x;
    if (n < 768) {
        int orig = n + (n >= 256 ? 256 : 0);
        bp[n] = bih[orig] + bhh[orig];
    }
}

__device__ __forceinline__ float sigf(float x) { return 1.f / (1.f + expf(-x)); }

__global__ void k_lstm_act(const float* __restrict__ bias, float* __restrict__ out,
                           int col_off, __half* __restrict__ hb) {
    size_t idx = (size_t)blockIdx.x * blockDim.x + threadIdx.x;
    if (idx >= (size_t)NN * HD) return;
    int n = (int)(idx >> 8);
    int j = (int)(idx & 255);
    size_t base = (size_t)n * 768;
    float ii = __half2float(g_Gh[base + j])       + bias[j];
    float gg = __half2float(g_Gh[base + 256 + j]) + bias[256 + j];
    float oo = __half2float(g_Gh[base + 512 + j]) + bias[512 + j];
    float c = sigf(ii) * tanhf(gg);
    float h = sigf(oo) * tanhf(c);
    out[(size_t)n * 768 + col_off + j] = h;
    if (hb) hb[idx] = __float2half(h);
}

__global__ void k_copy_x(const float* __restrict__ x, float* __restrict__ out) {
    size_t idx = (size_t)blockIdx.x * blockDim.x + threadIdx.x;
    if (idx >= (size_t)NN * IND) return;
    int n = (int)(idx >> 8);
    int j = (int)(idx & 255);
    out[(size_t)n * 768 + 512 + j] = x[idx];
}

// ---------------- FP16 mma.sync GEMM: C[M,N] = A[M,K] @ B[N,K]^T, 4-stage pipeline ----------------
// CTA tile 128x256, BK=32. 8 warps (2x4), warp tile 64x64. One barrier per K-step.
// Register-level fragment pipelining: both ks-slices' fragments loaded before the MMA block.
#define STAGES 4
#define AH_STRIDE 40
#define A_BUF (128 * AH_STRIDE)   // 5120 halfs per stage
#define B_BUF (256 * AH_STRIDE)   // 10240 halfs per stage
#define STG_BUF (A_BUF + B_BUF)   // 15360 halfs
#define GEMM_SMEM (STAGES * STG_BUF * 2)   // 122880 bytes

__device__ __forceinline__ void cp16(uint32_t saddr, const void* gptr, bool valid) {
    int sz = valid ? 16 : 0;
    asm volatile("cp.async.cg.shared.global [%0], [%1], 16, %2;\n"
                 :: "r"(saddr), "l"(gptr), "r"(sz) : "memory");
}

__device__ __forceinline__ void ldsm_x4(uint32_t& r0, uint32_t& r1, uint32_t& r2, uint32_t& r3,
                                        uint32_t addr) {
    asm volatile("ldmatrix.sync.aligned.m8n8.x4.shared.b16 {%0,%1,%2,%3}, [%4];"
                 : "=r"(r0), "=r"(r1), "=r"(r2), "=r"(r3) : "r"(addr));
}

__device__ __forceinline__ void mma_fp16(float* c, const uint32_t* a, const uint32_t* b) {
    asm volatile(
        "mma.sync.aligned.m16n8k16.row.col.f32.f16.f16.f32 "
        "{%0,%1,%2,%3}, {%4,%5,%6,%7}, {%8,%9}, {%0,%1,%2,%3};\n"
        : "+f"(c[0]), "+f"(c[1]), "+f"(c[2]), "+f"(c[3])
        : "r"(a[0]), "r"(a[1]), "r"(a[2]), "r"(a[3]), "r"(b[0]), "r"(b[1]));
}

__global__ __launch_bounds__(256, 1)
void k_gemm_fp16(int M, int K,
                 const __half* __restrict__ A, int lda,
                 const __half* __restrict__ B, int ldb,
                 __half* __restrict__ C, int ldc) {
    extern __shared__ __half smh[];

    const int tid  = threadIdx.x;
    const int lane = tid & 31;
    const int warp = tid >> 5;
    const int wr = warp >> 2;       // 0..1
    const int wc = warp & 3;        // 0..3
    const int row0 = blockIdx.y * 128;
    const int col0 = blockIdx.x * 256;

    float c[4][8][4];
#pragma unroll
    for (int i = 0; i < 4; i++)
#pragma unroll
        for (int j = 0; j < 8; j++)
#pragma unroll
            for (int k = 0; k < 4; k++) c[i][j][k] = 0.f;

    const int KT = K >> 5;

    auto loadTile = [&](int kt, int buf) {
        __half* as = smh + buf * STG_BUF;
        __half* bs = as + A_BUF;
        int k0 = kt * 32;
#pragma unroll
        for (int i = 0; i < 2; i++) {
            int idx = tid + i * 256;
            int r = idx >> 2, q = idx & 3;
            int gr = row0 + r;
            cp16(smem_u32(&as[r * AH_STRIDE + q * 8]),
                 A + (size_t)gr * lda + k0 + q * 8, gr < M);
        }
#pragma unroll
        for (int i = 0; i < 4; i++) {
            int idx = tid + i * 256;
            int r = idx >> 2, q = idx & 3;
            cp16(smem_u32(&bs[r * AH_STRIDE + q * 8]),
                 B + (size_t)(col0 + r) * ldb + k0 + q * 8, true);
        }
    };

    // prologue: stages 0..STAGES-2
#pragma unroll
    for (int s = 0; s < STAGES - 1; s++) {
        if (s < KT) loadTile(s, s);
        asm volatile("cp.async.commit_group;" ::: "memory");
    }

    for (int kt = 0; kt < KT; kt++) {
        asm volatile("cp.async.wait_group %0;" :: "n"(STAGES - 2) : "memory");
        __syncthreads();

        int lk = kt + STAGES - 1;
        if (lk < KT) loadTile(lk, lk % STAGES);
        asm volatile("cp.async.commit_group;" ::: "memory");

        const __half* as = smh + (kt % STAGES) * STG_BUF;
        const __half* bs = as + A_BUF;

        // ---- load ALL fragments for both ks slices, then issue all MMAs ----
        uint32_t a[2][4][4];
        uint32_t b[2][8][2];
#pragma unroll
        for (int ks = 0; ks < 2; ks++) {
            const int ko = ks * 16;
#pragma unroll
            for (int mi = 0; mi < 4; mi++) {
                int r = wr * 64 + mi * 16 + (lane & 15);
                uint32_t addr = smem_u32(&as[r * AH_STRIDE + ko + (lane >> 4) * 8]);
                ldsm_x4(a[ks][mi][0], a[ks][mi][1], a[ks][mi][2], a[ks][mi][3], addr);
            }
#pragma unroll
            for (int nj = 0; nj < 4; nj++) {
                int rb = wc * 64 + nj * 16 + (lane & 15);
                uint32_t addr = smem_u32(&bs[rb * AH_STRIDE + ko + (lane >> 4) * 8]);
                uint32_t r0, r1, r2, r3;
                ldsm_x4(r0, r1, r2, r3, addr);
                b[ks][2 * nj][0] = r0;     b[ks][2 * nj][1] = r2;
                b[ks][2 * nj + 1][0] = r1; b[ks][2 * nj + 1][1] = r3;
            }
        }
#pragma unroll
        for (int ks = 0; ks < 2; ks++)
#pragma unroll
            for (int mi = 0; mi < 4; mi++)
#pragma unroll
                for (int ni = 0; ni < 8; ni++)
                    mma_fp16(c[mi][ni], a[ks][mi], b[ks][ni]);
    }

    // epilogue: fp16 output
#pragma unroll
    for (int mi = 0; mi < 4; mi++) {
        int r = row0 + wr * 64 + mi * 16 + (lane >> 2);
#pragma unroll
        for (int ni = 0; ni < 8; ni++) {
            int cc = col0 + wc * 64 + ni * 8 + (lane & 3) * 2;
            if (r < M)
                *(__half2*)&C[(size_t)r * ldc + cc] = __floats2half2_rn(c[mi][ni][0], c[mi][ni][1]);
            if (r + 8 < M)
                *(__half2*)&C[(size_t)(r + 8) * ldc + cc] = __floats2half2_rn(c[mi][ni][2], c[mi][ni][3]);
        }
    }
}

// ---------------- launch ----------------
static inline int cdiv(long long a, long long b) { return (int)((a + b - 1) / b); }

extern "C" void kernel_launch(void* const* d_in, const int* in_sizes, int n_in,
                              void* d_out, int out_size) {
    const float* x    = (const float*)d_in[0];
    const int*   ei   = (const int*)d_in[1];
    const float* ew   = (const float*)d_in[2];
    const float* W1   = (const float*)d_in[3];
    const float* b1   = (const float*)d_in[4];
    const float* W2   = (const float*)d_in[5];
    const float* b2   = (const float*)d_in[6];
    const float* gm1  = (const float*)d_in[7];
    const float* bt1  = (const float*)d_in[8];
    const float* gm2  = (const float*)d_in[9];
    const float* bt2  = (const float*)d_in[10];
    const float* Wih1 = (const float*)d_in[11];
    const float* bih1 = (const float*)d_in[13];
    const float* bhh1 = (const float*)d_in[14];
    const float* Wih2 = (const float*)d_in[15];
    const float* bih2 = (const float*)d_in[17];
    const float* bhh2 = (const float*)d_in[18];
    float* out = (float*)d_out;

    static cudaStream_t s2, s3;
    static cudaEvent_t ev0, evCsr, evSide;
    static int inited = 0;
    if (!inited) {
        cudaFuncSetAttribute(k_gemm_fp16, cudaFuncAttributeMaxDynamicSharedMemorySize, GEMM_SMEM);
        cudaStreamCreateWithFlags(&s2, cudaStreamNonBlocking);
        cudaStreamCreateWithFlags(&s3, cudaStreamNonBlocking);
        cudaEventCreateWithFlags(&ev0, cudaEventDisableTiming);
        cudaEventCreateWithFlags(&evCsr, cudaEventDisableTiming);
        cudaEventCreateWithFlags(&evSide, cudaEventDisableTiming);
        inited = 1;
    }

    float *gbias1, *gbias2, *gsumA, *gsumsqA, *gsumB, *gsumsqB;
    __half *gxh, *gXcH, *ghL1h, *gW1h, *gW2h, *gB1h, *gB2h, *gXWh, *gGh;
    cudaGetSymbolAddress((void**)&gbias1, g_bias1);
    cudaGetSymbolAddress((void**)&gbias2, g_bias2);
    cudaGetSymbolAddress((void**)&gsumA, g_sumA);
    cudaGetSymbolAddress((void**)&gsumsqA, g_sumsqA);
    cudaGetSymbolAddress((void**)&gsumB, g_sumB);
    cudaGetSymbolAddress((void**)&gsumsqB, g_sumsqB);
    cudaGetSymbolAddress((void**)&gXWh, g_XWh);
    cudaGetSymbolAddress((void**)&gGh, g_Gh);
    cudaGetSymbolAddress((void**)&gxh, g_xh);
    cudaGetSymbolAddress((void**)&gXcH, g_XcH);
    cudaGetSymbolAddress((void**)&ghL1h, g_hL1h);
    cudaGetSymbolAddress((void**)&gW1h, g_W1h);
    cudaGetSymbolAddress((void**)&gW2h, g_W2h);
    cudaGetSymbolAddress((void**)&gB1h, g_B1h);
    cudaGetSymbolAddress((void**)&gB2h, g_B2h);

    const int nb_scan = cdiv(NN, 512);    // 98
    const int mt = cdiv(NN, 128);         // 391
    dim3 grid_h(1, mt);                   // N=256
    dim3 grid_l(3, mt);                   // N=768
    const int nh_blocks = cdiv((long long)NN * HD, 256);

    // ---- main stream prefix (GEMM1 stays in the profiled slot) ----
    cudaEventRecord(ev0, 0);
    k_tohalf<<<cdiv((long long)NN * IND / 4, 256), 256>>>(x, gxh, (long long)NN * IND);
    k_w_t<<<cdiv(256 * 256, 256), 256>>>(W1, gW1h);
    k_w_t<<<cdiv(256 * 256, 256), 256>>>(W2, gW2h);
    k_gemm_fp16<<<grid_h, 256, GEMM_SMEM>>>(NN, IND, gxh, IND, gW1h, IND, gXWh, HD);

    // ---- s2: CSR build chain ----
    cudaStreamWaitEvent(s2, ev0, 0);
    k_zero_nd<<<cdiv(NN, 256), 256, 0, s2>>>();
    k_deg_hist<<<cdiv(EE, 256), 256, 0, s2>>>(ei, ew);
    k_dinv<<<cdiv(NN, 256), 256, 0, s2>>>();
    k_norm<<<cdiv(EE, 256), 256, 0, s2>>>(ei, ew);
    k_scan1<<<nb_scan, 512, 0, s2>>>();
    k_scan2<<<1, 128, 0, s2>>>(nb_scan);
    k_scan3<<<cdiv(NN, 256), 256, 0, s2>>>();
    k_fill<<<cdiv(EE, 256), 256, 0, s2>>>(ei);
    cudaEventRecord(evCsr, s2);

    // ---- s3: LSTM weight packing + x copy ----
    cudaStreamWaitEvent(s3, ev0, 0);
    k_pack_w<<<cdiv(768LL * 512, 256), 256, 0, s3>>>(Wih1, gB1h, 512);
    k_pack_w<<<cdiv(768LL * 256, 256), 256, 0, s3>>>(Wih2, gB2h, 256);
    k_pack_bias<<<3, 256, 0, s3>>>(bih1, bhh1, gbias1);
    k_pack_bias<<<3, 256, 0, s3>>>(bih2, bhh2, gbias2);
    k_copy_x<<<cdiv((long long)NN * IND, 256), 256, 0, s3>>>(x, out);
    cudaEventRecord(evSide, s3);

    // ---- join CSR before aggregation ----
    cudaStreamWaitEvent(0, evCsr, 0);

    // ----- GCN layer 1 -----
    k_aggregate<<<NN, 256>>>(ei, b1);
    k_bn_stats<<<cdiv(NN, 32), 256>>>(gsumA, gsumsqA);
    k_bn_apply<<<nh_blocks, 256>>>(0, gsumA, gsumsqA, gm1, bt1);

    // ----- GCN layer 2 -----
    k_gemm_fp16<<<grid_h, 256, GEMM_SMEM>>>(NN, HD, gXcH, 512, gW2h, HD, gXWh, HD);
    k_aggregate<<<NN, 256>>>(ei, b2);
    k_bn_stats<<<cdiv(NN, 32), 256>>>(gsumB, gsumsqB);
    k_bn_apply<<<nh_blocks, 256>>>(256, gsumB, gsumsqB, gm2, bt2);

    // ---- join packing/copy before LSTM GEMMs ----
    cudaStreamWaitEvent(0, evSide, 0);

    // ----- LSTM 1: gates = Xc @ B1^T  (K=512, N=768) -----
    k_gemm_fp16<<<grid_l, 256, GEMM_SMEM>>>(NN, 512, gXcH, 512, gB1h, 512, gGh, 768);
    k_lstm_act<<<nh_blocks, 256>>>(gbias1, out, 0, ghL1h);

    // ----- LSTM 2: gates = hL1 @ B2^T (K=256, N=768) -----
    k_gemm_fp16<<<grid_l, 256, GEMM_SMEM>>>(NN, 256, ghL1h, 256, gB2h, 256, gGh, 768);
    k_lstm_act<<<nh_blocks, 256>>>(gbias2, out, 256, (__half*)0);
}

// round 16
// speedup vs baseline: 1.0474x; 1.0474x over previous
#include <cuda_runtime.h>
#include <cuda_fp16.h>
#include <stdint.h>
#include <math.h>

#define NN 50000
#define EE 800000
#define IND 256
#define HD  256
#define EPS 1e-5f

// ---------------- scratch (device globals; no allocation allowed) ----------------
__device__ __align__(16) float g_deg[NN];
__device__ __align__(16) float g_dinv[NN];
__device__ __align__(16) float g_norm[EE];
__device__ __align__(16) float g_snorm[NN];                  // sum of norm per dst
__device__ __align__(16) __half g_XWh[(size_t)NN * HD];      // GEMM out (fp16), gather source
__device__ __align__(16) __half g_Gh[(size_t)NN * 768];      // packed LSTM gates (i,g,o) fp16
__device__ __align__(16) __half g_xh[(size_t)NN * IND];      // fp16 x
__device__ __align__(16) __half g_XcH[(size_t)NN * 512];     // fp16 [v1|v2] (raw relu'd), stride 512
__device__ __align__(16) __half g_hL1h[(size_t)NN * HD];     // fp16 hL1
__device__ __align__(16) __half g_W1h[HD * IND];             // W1^T [N,K]
__device__ __align__(16) __half g_W2h[HD * HD];              // sc1-scaled W2^T [N,K]
__device__ __align__(16) __half g_B1h[768 * 512];            // sc-scaled packed Wih1 [N=768,K=512]
__device__ __align__(16) __half g_B2h[768 * 256];            // packed Wih2 [N=768,K=256]
__device__ __align__(16) float g_bias1[768];
__device__ __align__(16) float g_bias2[768];
__device__ __align__(16) float g_sumA[HD];
__device__ __align__(16) float g_sumsqA[HD];
__device__ __align__(16) float g_sumB[HD];
__device__ __align__(16) float g_sumsqB[HD];
__device__ __align__(16) float g_sc[512];    // [0:256) layer1, [256:512) layer2
__device__ __align__(16) float g_sh[512];
__device__ __align__(16) float g_c2[256];    // sh1 @ W2
__device__ __align__(16) float g_cg[768];    // sh @ B1^T
// CSR
__device__ int g_cnt[NN];
__device__ int g_rowptr[NN + 1];
__device__ int g_eidx[EE];
__device__ int g_bsum[128];

__device__ __forceinline__ uint32_t smem_u32(const void* p) {
    uint32_t a;
    asm("{ .reg .u64 t; cvta.to.shared.u64 t, %1; cvt.u32.u64 %0, t; }" : "=r"(a) : "l"(p));
    return a;
}

// ---------------- degree / norm / CSR build ----------------
__global__ void k_zero_nd() {
    int i = blockIdx.x * blockDim.x + threadIdx.x;
    if (i < NN) { g_deg[i] = 0.f; g_cnt[i] = 0; g_snorm[i] = 0.f; }
    if (i < HD) { g_sumA[i] = 0.f; g_sumsqA[i] = 0.f; g_sumB[i] = 0.f; g_sumsqB[i] = 0.f; }
}

__global__ void k_deg_hist(const int* __restrict__ ei, const float* __restrict__ ew) {
    int e = blockIdx.x * blockDim.x + threadIdx.x;
    if (e < EE) {
        int d = ei[EE + e];
        atomicAdd(&g_deg[d], ew[e]);
        atomicAdd(&g_cnt[d], 1);
    }
}

__global__ void k_dinv() {
    int i = blockIdx.x * blockDim.x + threadIdx.x;
    if (i < NN) g_dinv[i] = rsqrtf(g_deg[i] + 1.0f);
}

__global__ void k_norm(const int* __restrict__ ei, const float* __restrict__ ew) {
    int e = blockIdx.x * blockDim.x + threadIdx.x;
    if (e < EE) {
        int s = ei[e], d = ei[EE + e];
        float nv = g_dinv[s] * ew[e] * g_dinv[d];
        g_norm[e] = nv;
        atomicAdd(&g_snorm[d], nv);
    }
}

__global__ void k_scan1() {
    __shared__ int s[512];
    int tid = threadIdx.x;
    int i = blockIdx.x * 512 + tid;
    int v = (i < NN) ? g_cnt[i] : 0;
    s[tid] = v;
    __syncthreads();
    for (int off = 1; off < 512; off <<= 1) {
        int t = (tid >= off) ? s[tid - off] : 0;
        __syncthreads();
        s[tid] += t;
        __syncthreads();
    }
    if (i < NN) g_rowptr[i + 1] = s[tid];
    if (tid == 511) g_bsum[blockIdx.x] = s[511];
}

__global__ void k_scan2(int nb) {
    __shared__ int s[128];
    int tid = threadIdx.x;
    int v = (tid < nb) ? g_bsum[tid] : 0;
    s[tid] = v;
    __syncthreads();
    for (int off = 1; off < 128; off <<= 1) {
        int t = (tid >= off) ? s[tid - off] : 0;
        __syncthreads();
        s[tid] += t;
        __syncthreads();
    }
    if (tid < nb) g_bsum[tid] = s[tid];
}

__global__ void k_scan3() {
    int i = blockIdx.x * blockDim.x + threadIdx.x;
    if (i < NN) {
        int b = i >> 9;
        int add = (b > 0) ? g_bsum[b - 1] : 0;
        g_rowptr[i + 1] += add;
        g_cnt[i] = 0;
    }
    if (i == 0) g_rowptr[0] = 0;
}

__global__ void k_fill(const int* __restrict__ ei) {
    int e = blockIdx.x * blockDim.x + threadIdx.x;
    if (e < EE) {
        int d = ei[EE + e];
        int pos = atomicAdd(&g_cnt[d], 1);
        g_eidx[g_rowptr[d] + pos] = e;
    }
}

// ---------------- CSR aggregation -> relu -> fp16 Vc[:, out_col:+256] ----------------
// cvec != null (layer 2): adds cvec[j]*s_n where s_n = snorm[n] + dinv^2.
__global__ __launch_bounds__(256)
void k_aggregate(const int* __restrict__ ei, const float* __restrict__ bias,
                 const float* __restrict__ cvec, int out_col) {
    __shared__ float part[7][256];
    int n = blockIdx.x;
    int t = threadIdx.x;
    int w = t >> 5;
    int j = t & 31;          // uint4 index: 8 halfs each
    const uint4* XW = (const uint4*)g_XWh;

    float acc[8];
#pragma unroll
    for (int p = 0; p < 8; p++) acc[p] = 0.f;

    int beg = g_rowptr[n], end = g_rowptr[n + 1];
    for (int k = beg + w; k < end; k += 8) {
        int e = g_eidx[k];
        float wgt = g_norm[e];
        int s = ei[e];
        uint4 v = XW[(size_t)s * 32 + j];
        const __half2* h2 = (const __half2*)&v;
#pragma unroll
        for (int p = 0; p < 4; p++) {
            float2 f = __half22float2(h2[p]);
            acc[2 * p]     += f.x * wgt;
            acc[2 * p + 1] += f.y * wgt;
        }
    }
    if (w) {
#pragma unroll
        for (int p = 0; p < 8; p++) part[w - 1][j * 8 + p] = acc[p];
    }
    __syncthreads();
    if (w == 0) {
#pragma unroll
        for (int q = 0; q < 7; q++)
#pragma unroll
            for (int p = 0; p < 8; p++) acc[p] += part[q][j * 8 + p];
        float d = g_dinv[n]; d *= d;
        uint4 sv = XW[(size_t)n * 32 + j];
        const __half2* sh2 = (const __half2*)&sv;
        float r[8];
#pragma unroll
        for (int p = 0; p < 4; p++) {
            float2 f = __half22float2(sh2[p]);
            r[2 * p]     = acc[2 * p]     + f.x * d;
            r[2 * p + 1] = acc[2 * p + 1] + f.y * d;
        }
        if (cvec) {
            float s_n = g_snorm[n] + d;
#pragma unroll
            for (int p = 0; p < 8; p++) r[p] += cvec[j * 8 + p] * s_n;
        }
        const float4* b4 = (const float4*)bias;
        float4 ba = b4[j * 2], bb = b4[j * 2 + 1];
        r[0] = fmaxf(r[0] + ba.x, 0.f); r[1] = fmaxf(r[1] + ba.y, 0.f);
        r[2] = fmaxf(r[2] + ba.z, 0.f); r[3] = fmaxf(r[3] + ba.w, 0.f);
        r[4] = fmaxf(r[4] + bb.x, 0.f); r[5] = fmaxf(r[5] + bb.y, 0.f);
        r[6] = fmaxf(r[6] + bb.z, 0.f); r[7] = fmaxf(r[7] + bb.w, 0.f);
        uint4 ov;
        __half2* oh = (__half2*)&ov;
        oh[0] = __floats2half2_rn(r[0], r[1]);
        oh[1] = __floats2half2_rn(r[2], r[3]);
        oh[2] = __floats2half2_rn(r[4], r[5]);
        oh[3] = __floats2half2_rn(r[6], r[7]);
        *(uint4*)&g_XcH[(size_t)n * 512 + out_col + j * 8] = ov;
    }
}

// ---------------- misc elementwise ----------------
__global__ void k_tohalf(const float* __restrict__ in, __half* __restrict__ out, long long n) {
    long long i = ((long long)blockIdx.x * blockDim.x + threadIdx.x) * 4;
    if (i + 3 < n) {
        float4 v = *(const float4*)&in[i];
        *(__half2*)&out[i]     = __floats2half2_rn(v.x, v.y);
        *(__half2*)&out[i + 2] = __floats2half2_rn(v.z, v.w);
    } else {
        for (long long k = i; k < n; k++) out[k] = __float2half(in[k]);
    }
}

// W1 [K=256,N=256] -> half [N,K]
__global__ void k_w_t(const float* __restrict__ W, __half* __restrict__ Wt) {
    int idx = blockIdx.x * blockDim.x + threadIdx.x;
    if (idx >= 256 * 256) return;
    int n = idx >> 8, k = idx & 255;
    Wt[n * 256 + k] = __float2half(W[k * 256 + n]);
}

// stats over Vc[:, col:col+256] (fp16)
__global__ void k_bn_stats(int col, float* __restrict__ sum, float* __restrict__ sumsq) {
    const int ROWS = 32;
    int j = threadIdx.x;
    int r0 = blockIdx.x * ROWS;
    int r1 = min(r0 + ROWS, NN);
    float s = 0.f, sq = 0.f;
    for (int r = r0; r < r1; r++) {
        float v = __half2float(g_XcH[(size_t)r * 512 + col + j]);
        s += v; sq += v * v;
    }
    atomicAdd(&sum[j], s);
    atomicAdd(&sumsq[j], sq);
}

// sc/sh from sums (one block, 256 threads); writes g_sc/g_sh at offset
__global__ void k_bn_coef(const float* __restrict__ sum, const float* __restrict__ sumsq,
                          const float* __restrict__ gamma, const float* __restrict__ beta,
                          int off) {
    int j = threadIdx.x;
    float mu  = sum[j] * (1.f / (float)NN);
    float var = sumsq[j] * (1.f / (float)NN) - mu * mu;
    float sc  = gamma[j] * rsqrtf(var + EPS);
    g_sc[off + j] = sc;
    g_sh[off + j] = beta[j] - mu * sc;
}

// c2[j] = sum_k sh1[k] * W2[k*256+j]   (one block, 256 threads)
__global__ void k_gemv_c2(const float* __restrict__ W2) {
    int j = threadIdx.x;
    float s = 0.f;
    for (int k = 0; k < 256; k++) s += g_sh[k] * W2[k * 256 + j];
    g_c2[j] = s;
}

// W2h[n,k] = half(W2[k,n] * sc1[k])
__global__ void k_scale_w2(const float* __restrict__ W2) {
    int idx = blockIdx.x * blockDim.x + threadIdx.x;
    if (idx >= 256 * 256) return;
    int n = idx >> 8, k = idx & 255;
    g_W2h[n * 256 + k] = __float2half(W2[k * 256 + n] * g_sc[k]);
}

// cg[g] = sum_k g_sh[k] * Wih1[orig(g)*512+k]  — one warp per output row
__global__ void k_gemv_cg(const float* __restrict__ Wih1) {
    int gw = blockIdx.x * 8 + (threadIdx.x >> 5);   // 0..767
    int lane = threadIdx.x & 31;
    int orig = gw + (gw >= 256 ? 256 : 0);
    const float* row = Wih1 + (size_t)orig * 512;
    float s = 0.f;
    for (int k = lane; k < 512; k += 32) s += g_sh[k] * row[k];
#pragma unroll
    for (int o = 16; o > 0; o >>= 1) s += __shfl_xor_sync(0xffffffff, s, o);
    if (lane == 0) g_cg[gw] = s;
}

// B1h[g,k] = half(Wih1[orig(g)*512+k] * g_sc[k])
__global__ void k_scale_b1(const float* __restrict__ Wih1) {
    size_t idx = (size_t)blockIdx.x * blockDim.x + threadIdx.x;
    if (idx >= (size_t)768 * 512) return;
    int g = (int)(idx >> 9);
    int k = (int)(idx & 511);
    int orig = g + (g >= 256 ? 256 : 0);
    g_B1h[idx] = __float2half(Wih1[(size_t)orig * 512 + k] * g_sc[k]);
}

__global__ void k_pack_w(const float* __restrict__ Wih, __half* __restrict__ Bp, int Kdim) {
    size_t idx = (size_t)blockIdx.x * blockDim.x + threadIdx.x;
    if (idx >= (size_t)768 * Kdim) return;
    int n = (int)(idx / Kdim);
    int k = (int)(idx % Kdim);
    int orig = n + (n >= 256 ? 256 : 0);
    Bp[idx] = __float2half(Wih[(size_t)orig * Kdim + k]);
}

__global__ void k_pack_bias(const float* __restrict__ bih, const float* __restrict__ bhh,
                            float* __restrict__ bp) {
    int n = blockIdx.x * blockDim.x + threadIdx.x;
    if (n < 768) {
        int orig = n + (n >= 256 ? 256 : 0);
        bp[n] = bih[orig] + bhh[orig];
    }
}

__device__ __forceinline__ float sigf(float x) { return 1.f / (1.f + expf(-x)); }

__global__ void k_lstm_act(const float* __restrict__ bias, const float* __restrict__ cg,
                           float* __restrict__ out, int col_off, __half* __restrict__ hb) {
    size_t idx = (size_t)blockIdx.x * blockDim.x + threadIdx.x;
    if (idx >= (size_t)NN * HD) return;
    int n = (int)(idx >> 8);
    int j = (int)(idx & 255);
    size_t base = (size_t)n * 768;
    float ci = cg ? cg[j] : 0.f;
    float cgg = cg ? cg[256 + j] : 0.f;
    float co = cg ? cg[512 + j] : 0.f;
    float ii = __half2float(g_Gh[base + j])       + bias[j]       + ci;
    float gg = __half2float(g_Gh[base + 256 + j]) + bias[256 + j] + cgg;
    float oo = __half2float(g_Gh[base + 512 + j]) + bias[512 + j] + co;
    float c = sigf(ii) * tanhf(gg);
    float h = sigf(oo) * tanhf(c);
    out[(size_t)n * 768 + col_off + j] = h;
    if (hb) hb[idx] = __float2half(h);
}

__global__ void k_copy_x(const float* __restrict__ x, float* __restrict__ out) {
    size_t idx = (size_t)blockIdx.x * blockDim.x + threadIdx.x;
    if (idx >= (size_t)NN * IND) return;
    int n = (int)(idx >> 8);
    int j = (int)(idx & 255);
    out[(size_t)n * 768 + 512 + j] = x[idx];
}

// ---------------- FP16 mma.sync GEMM (R14 config): 128x256, BK=32, 4 stages ----------------
#define STAGES 4
#define AH_STRIDE 40
#define A_BUF (128 * AH_STRIDE)
#define B_BUF (256 * AH_STRIDE)
#define STG_BUF (A_BUF + B_BUF)
#define GEMM_SMEM (STAGES * STG_BUF * 2)   // 122880 bytes

__device__ __forceinline__ void cp16(uint32_t saddr, const void* gptr, bool valid) {
    int sz = valid ? 16 : 0;
    asm volatile("cp.async.cg.shared.global [%0], [%1], 16, %2;\n"
                 :: "r"(saddr), "l"(gptr), "r"(sz) : "memory");
}

__device__ __forceinline__ void ldsm_x4(uint32_t& r0, uint32_t& r1, uint32_t& r2, uint32_t& r3,
                                        uint32_t addr) {
    asm volatile("ldmatrix.sync.aligned.m8n8.x4.shared.b16 {%0,%1,%2,%3}, [%4];"
                 : "=r"(r0), "=r"(r1), "=r"(r2), "=r"(r3) : "r"(addr));
}

__device__ __forceinline__ void mma_fp16(float* c, const uint32_t* a, const uint32_t* b) {
    asm volatile(
        "mma.sync.aligned.m16n8k16.row.col.f32.f16.f16.f32 "
        "{%0,%1,%2,%3}, {%4,%5,%6,%7}, {%8,%9}, {%0,%1,%2,%3};\n"
        : "+f"(c[0]), "+f"(c[1]), "+f"(c[2]), "+f"(c[3])
        : "r"(a[0]), "r"(a[1]), "r"(a[2]), "r"(a[3]), "r"(b[0]), "r"(b[1]));
}

__global__ __launch_bounds__(256, 1)
void k_gemm_fp16(int M, int K,
                 const __half* __restrict__ A, int lda,
                 const __half* __restrict__ B, int ldb,
                 __half* __restrict__ C, int ldc) {
    extern __shared__ __half smh[];

    const int tid  = threadIdx.x;
    const int lane = tid & 31;
    const int warp = tid >> 5;
    const int wr = warp >> 2;
    const int wc = warp & 3;
    const int row0 = blockIdx.y * 128;
    const int col0 = blockIdx.x * 256;

    float c[4][8][4];
#pragma unroll
    for (int i = 0; i < 4; i++)
#pragma unroll
        for (int j = 0; j < 8; j++)
#pragma unroll
            for (int k = 0; k < 4; k++) c[i][j][k] = 0.f;

    const int KT = K >> 5;

    auto loadTile = [&](int kt, int buf) {
        __half* as = smh + buf * STG_BUF;
        __half* bs = as + A_BUF;
        int k0 = kt * 32;
#pragma unroll
        for (int i = 0; i < 2; i++) {
            int idx = tid + i * 256;
            int r = idx >> 2, q = idx & 3;
            int gr = row0 + r;
            cp16(smem_u32(&as[r * AH_STRIDE + q * 8]),
                 A + (size_t)gr * lda + k0 + q * 8, gr < M);
        }
#pragma unroll
        for (int i = 0; i < 4; i++) {
            int idx = tid + i * 256;
            int r = idx >> 2, q = idx & 3;
            cp16(smem_u32(&bs[r * AH_STRIDE + q * 8]),
                 B + (size_t)(col0 + r) * ldb + k0 + q * 8, true);
        }
    };

#pragma unroll
    for (int s = 0; s < STAGES - 1; s++) {
        if (s < KT) loadTile(s, s);
        asm volatile("cp.async.commit_group;" ::: "memory");
    }

    for (int kt = 0; kt < KT; kt++) {
        asm volatile("cp.async.wait_group %0;" :: "n"(STAGES - 2) : "memory");
        __syncthreads();

        int lk = kt + STAGES - 1;
        if (lk < KT) loadTile(lk, lk % STAGES);
        asm volatile("cp.async.commit_group;" ::: "memory");

        const __half* as = smh + (kt % STAGES) * STG_BUF;
        const __half* bs = as + A_BUF;
#pragma unroll
        for (int ks = 0; ks < 2; ks++) {
            const int ko = ks * 16;
            uint32_t a[4][4];
#pragma unroll
            for (int mi = 0; mi < 4; mi++) {
                int r = wr * 64 + mi * 16 + (lane & 15);
                uint32_t addr = smem_u32(&as[r * AH_STRIDE + ko + (lane >> 4) * 8]);
                ldsm_x4(a[mi][0], a[mi][1], a[mi][2], a[mi][3], addr);
            }
            uint32_t b[8][2];
#pragma unroll
            for (int nj = 0; nj < 4; nj++) {
                int rb = wc * 64 + nj * 16 + (lane & 15);
                uint32_t addr = smem_u32(&bs[rb * AH_STRIDE + ko + (lane >> 4) * 8]);
                uint32_t r0, r1, r2, r3;
                ldsm_x4(r0, r1, r2, r3, addr);
                b[2 * nj][0] = r0;     b[2 * nj][1] = r2;
                b[2 * nj + 1][0] = r1; b[2 * nj + 1][1] = r3;
            }
#pragma unroll
            for (int mi = 0; mi < 4; mi++)
#pragma unroll
                for (int ni = 0; ni < 8; ni++)
                    mma_fp16(c[mi][ni], a[mi], b[ni]);
        }
    }

#pragma unroll
    for (int mi = 0; mi < 4; mi++) {
        int r = row0 + wr * 64 + mi * 16 + (lane >> 2);
#pragma unroll
        for (int ni = 0; ni < 8; ni++) {
            int cc = col0 + wc * 64 + ni * 8 + (lane & 3) * 2;
            if (r < M)
                *(__half2*)&C[(size_t)r * ldc + cc] = __floats2half2_rn(c[mi][ni][0], c[mi][ni][1]);
            if (r + 8 < M)
                *(__half2*)&C[(size_t)(r + 8) * ldc + cc] = __floats2half2_rn(c[mi][ni][2], c[mi][ni][3]);
        }
    }
}

// ---------------- launch ----------------
static inline int cdiv(long long a, long long b) { return (int)((a + b - 1) / b); }

extern "C" void kernel_launch(void* const* d_in, const int* in_sizes, int n_in,
                              void* d_out, int out_size) {
    const float* x    = (const float*)d_in[0];
    const int*   ei   = (const int*)d_in[1];
    const float* ew   = (const float*)d_in[2];
    const float* W1   = (const float*)d_in[3];
    const float* b1   = (const float*)d_in[4];
    const float* W2   = (const float*)d_in[5];
    const float* b2   = (const float*)d_in[6];
    const float* gm1  = (const float*)d_in[7];
    const float* bt1  = (const float*)d_in[8];
    const float* gm2  = (const float*)d_in[9];
    const float* bt2  = (const float*)d_in[10];
    const float* Wih1 = (const float*)d_in[11];
    const float* bih1 = (const float*)d_in[13];
    const float* bhh1 = (const float*)d_in[14];
    const float* Wih2 = (const float*)d_in[15];
    const float* bih2 = (const float*)d_in[17];
    const float* bhh2 = (const float*)d_in[18];
    float* out = (float*)d_out;

    static cudaStream_t s2, s3;
    static cudaEvent_t ev0, evCsr, evSide;
    static int inited = 0;
    if (!inited) {
        cudaFuncSetAttribute(k_gemm_fp16, cudaFuncAttributeMaxDynamicSharedMemorySize, GEMM_SMEM);
        cudaStreamCreateWithFlags(&s2, cudaStreamNonBlocking);
        cudaStreamCreateWithFlags(&s3, cudaStreamNonBlocking);
        cudaEventCreateWithFlags(&ev0, cudaEventDisableTiming);
        cudaEventCreateWithFlags(&evCsr, cudaEventDisableTiming);
        cudaEventCreateWithFlags(&evSide, cudaEventDisableTiming);
        inited = 1;
    }

    float *gbias1, *gbias2, *gsumA, *gsumsqA, *gsumB, *gsumsqB, *gc2, *gcg;
    __half *gxh, *gXcH, *ghL1h, *gW1h, *gW2h, *gB1h, *gB2h, *gXWh, *gGh;
    cudaGetSymbolAddress((void**)&gbias1, g_bias1);
    cudaGetSymbolAddress((void**)&gbias2, g_bias2);
    cudaGetSymbolAddress((void**)&gsumA, g_sumA);
    cudaGetSymbolAddress((void**)&gsumsqA, g_sumsqA);
    cudaGetSymbolAddress((void**)&gsumB, g_sumB);
    cudaGetSymbolAddress((void**)&gsumsqB, g_sumsqB);
    cudaGetSymbolAddress((void**)&gc2, g_c2);
    cudaGetSymbolAddress((void**)&gcg, g_cg);
    cudaGetSymbolAddress((void**)&gXWh, g_XWh);
    cudaGetSymbolAddress((void**)&gGh, g_Gh);
    cudaGetSymbolAddress((void**)&gxh, g_xh);
    cudaGetSymbolAddress((void**)&gXcH, g_XcH);
    cudaGetSymbolAddress((void**)&ghL1h, g_hL1h);
    cudaGetSymbolAddress((void**)&gW1h, g_W1h);
    cudaGetSymbolAddress((void**)&gW2h, g_W2h);
    cudaGetSymbolAddress((void**)&gB1h, g_B1h);
    cudaGetSymbolAddress((void**)&gB2h, g_B2h);

    const int nb_scan = cdiv(NN, 512);    // 98
    const int mt = cdiv(NN, 128);         // 391
    dim3 grid_h(1, mt);                   // N=256
    dim3 grid_l(3, mt);                   // N=768
    const int nh_blocks = cdiv((long long)NN * HD, 256);

    // ---- main stream prefix (GEMM1 in profiled slot) ----
    cudaEventRecord(ev0, 0);
    k_tohalf<<<cdiv((long long)NN * IND / 4, 256), 256>>>(x, gxh, (long long)NN * IND);
    k_w_t<<<cdiv(256 * 256, 256), 256>>>(W1, gW1h);
    k_zero_nd<<<cdiv(NN, 256), 256>>>();
    k_gemm_fp16<<<grid_h, 256, GEMM_SMEM>>>(NN, IND, gxh, IND, gW1h, IND, gXWh, HD);

    // ---- s2: CSR build chain (depends on zero_nd -> keep after it via ev0? zero_nd is on main)
    // CSR chain needs g_deg/g_cnt/g_snorm zeroed; zero_nd runs on main before GEMM1.
    // Fork AFTER zero_nd: record event post-zero.
    cudaEventRecord(evCsr, 0);   // reuse evCsr as "zero done" marker temporarily? No — use separate logic:
    // (evCsr is re-recorded below as the real CSR-done event; this record is consumed by s2 wait)
    cudaStreamWaitEvent(s2, evCsr, 0);
    k_deg_hist<<<cdiv(EE, 256), 256, 0, s2>>>(ei, ew);
    k_dinv<<<cdiv(NN, 256), 256, 0, s2>>>();
    k_norm<<<cdiv(EE, 256), 256, 0, s2>>>(ei, ew);
    k_scan1<<<nb_scan, 512, 0, s2>>>();
    k_scan2<<<1, 128, 0, s2>>>(nb_scan);
    k_scan3<<<cdiv(NN, 256), 256, 0, s2>>>();
    k_fill<<<cdiv(EE, 256), 256, 0, s2>>>(ei);
    cudaEventRecord(evCsr, s2);

    // ---- s3: LSTM2 weight packing + biases + x copy ----
    cudaStreamWaitEvent(s3, ev0, 0);
    k_pack_w<<<cdiv(768LL * 256, 256), 256, 0, s3>>>(Wih2, gB2h, 256);
    k_pack_bias<<<3, 256, 0, s3>>>(bih1, bhh1, gbias1);
    k_pack_bias<<<3, 256, 0, s3>>>(bih2, bhh2, gbias2);
    k_copy_x<<<cdiv((long long)NN * IND, 256), 256, 0, s3>>>(x, out);
    cudaEventRecord(evSide, s3);

    // ---- join CSR before aggregation ----
    cudaStreamWaitEvent(0, evCsr, 0);

    // ----- GCN layer 1: aggregate -> Vc[:,0:256]; stats; fold BN1 into W2/B1 paths -----
    k_aggregate<<<NN, 256>>>(ei, b1, (const float*)0, 0);
    k_bn_stats<<<cdiv(NN, 32), 256>>>(0, gsumA, gsumsqA);
    k_bn_coef<<<1, 256>>>(gsumA, gsumsqA, gm1, bt1, 0);
    k_gemv_c2<<<1, 256>>>(W2);
    k_scale_w2<<<cdiv(256 * 256, 256), 256>>>(W2);

    // ----- GCN layer 2: XW2' = Vc(h1 raw) @ W2'; aggregate with c2*s_n -----
    k_gemm_fp16<<<grid_h, 256, GEMM_SMEM>>>(NN, HD, gXcH, 512, gW2h, HD, gXWh, HD);
    k_aggregate<<<NN, 256>>>(ei, b2, gc2, 256);
    k_bn_stats<<<cdiv(NN, 32), 256>>>(256, gsumB, gsumsqB);
    k_bn_coef<<<1, 256>>>(gsumB, gsumsqB, gm2, bt2, 256);
    k_gemv_cg<<<96, 256>>>(Wih1);
    k_scale_b1<<<cdiv(768LL * 512, 256), 256>>>(Wih1);

    // ---- join packing/copy before LSTM GEMMs ----
    cudaStreamWaitEvent(0, evSide, 0);

    // ----- LSTM 1: gates = Vc @ B1'^T + (bias + cg) -----
    k_gemm_fp16<<<grid_l, 256, GEMM_SMEM>>>(NN, 512, gXcH, 512, gB1h, 512, gGh, 768);
    k_lstm_act<<<nh_blocks, 256>>>(gbias1, gcg, out, 0, ghL1h);

    // ----- LSTM 2: gates = hL1 @ B2^T -----
    k_gemm_fp16<<<grid_l, 256, GEMM_SMEM>>>(NN, 256, ghL1h, 256, gB2h, 256, gGh, 768);
    k_lstm_act<<<nh_blocks, 256>>>(gbias2, (const float*)0, out, 256, (__half*)0);
}